// round 9
// baseline (speedup 1.0000x reference)
#include <cuda_runtime.h>
#include <cstdint>

// ---------------- problem constants ----------------
#define BS    32
#define SL    2048
#define MEMD  2048                // K of the big GEMM
#define HID   1024                // N of the big GEMM
#define IND   1024
#define MTOT  (BS * SL)           // 65536 GEMM rows (M)
#define OUT_SCORE_OFF (BS * MEMD) // context [32,2048] first, then score [32,2048]

// ---------------- GEMM tiling ----------------
#define TM       128
#define TN       256
#define KC       64               // K elems per stage = 2 sub-tiles of 32
#define NKITER   (MEMD / KC)      // 32
#define HALF_A   (TM * 32 * 4)              // 16384 B
#define HALF_B   (TN * 32 * 4)              // 32768 B
#define HALF_BYTES (HALF_A + HALF_B)        // 49152 B
#define STG_BYTES  (2 * HALF_BYTES)         // 98304 B
#define SMEM_GEMM  (2 * STG_BYTES)          // 196608 B (2 stages)

// ---------------- context tiling ----------------
#define SCH   16
#define SROWS (SL / SCH)          // 128

// ---------------- device scratch (static, no allocations) ----------------
__device__ float g_W2T[HID * MEMD];            // W2 transposed: [h][d], K-major
__device__ float g_hx[BS * HID];               // x@W1 + b1 + b2
// logit partials: [N-block][wn-warp][row] — one writer per slot, deterministic
__device__ float g_logitsp[4][4][MTOT];
__device__ float4 g_ctxp[SCH][BS][MEMD / 4];   // context partials, 4 MB

// ---------------- helpers ----------------
__device__ __forceinline__ uint32_t smem_u32(const void* p) {
    uint32_t a;
    asm("{ .reg .u64 t; cvta.to.shared.u64 t, %1; cvt.u32.u64 %0, t; }" : "=r"(a) : "l"(p));
    return a;
}
#define CP_ASYNC16(dst, src) \
    asm volatile("cp.async.cg.shared.global [%0], [%1], 16;" :: "r"(dst), "l"(src) : "memory")
#define CP_COMMIT() asm volatile("cp.async.commit_group;" ::: "memory")
#define CP_WAIT0()  asm volatile("cp.async.wait_group 0;" ::: "memory")

// ldmatrix x4: four 8x8 b16 tiles == four 8x4 f32 tiles; lands in tf32 fragment layout
#define LDSM4(r, addr) \
    asm volatile("ldmatrix.sync.aligned.m8n8.x4.shared.b16 {%0,%1,%2,%3}, [%4];" \
        : "=r"((r)[0]), "=r"((r)[1]), "=r"((r)[2]), "=r"((r)[3]) : "r"(addr))

// tf32 MMA, fp32 accumulate (legacy tensor path; sm_100 base target)
__device__ __forceinline__ void mma_tf32(float* c, const uint32_t* a, const uint32_t* b) {
    asm volatile(
        "mma.sync.aligned.m16n8k8.row.col.f32.tf32.tf32.f32 "
        "{%0,%1,%2,%3}, {%4,%5,%6,%7}, {%8,%9}, {%0,%1,%2,%3};"
        : "+f"(c[0]), "+f"(c[1]), "+f"(c[2]), "+f"(c[3])
        : "r"(a[0]), "r"(a[1]), "r"(a[2]), "r"(a[3]), "r"(b[0]), "r"(b[1]));
}

__device__ __forceinline__ float fast_tanh(float x) {
    float t; asm("tanh.approx.f32 %0, %1;" : "=f"(t) : "f"(x));
    return t;
}

// ============================================================
// Half-stage loader: A [128 x 32] + B [256 x 32] fp32, swizzled
// row layout: 8 chunks of 16 B, chunk index XOR (row & 7)
// ============================================================
__device__ __forceinline__ void load_half(
    int tid, uint32_t st,
    const float* __restrict__ Ag, const float* __restrict__ Bg)
{
    #pragma unroll
    for (int o = tid; o < TM * 8; o += 256) {
        int r = o >> 3, ch = o & 7;
        uint32_t dst = st + (uint32_t)(r * 128 + ((ch ^ (r & 7)) << 4));
        CP_ASYNC16(dst, Ag + (long)r * MEMD + ch * 4);
    }
    #pragma unroll
    for (int o = tid; o < TN * 8; o += 256) {
        int r = o >> 3, ch = o & 7;
        uint32_t dst = st + HALF_A + (uint32_t)(r * 128 + ((ch ^ (r & 7)) << 4));
        CP_ASYNC16(dst, Bg + (long)r * MEMD + ch * 4);
    }
}

// ============================================================
// GEMM (memory @ W2T) fused with tanh/v-dot reduction -> logit partials
// grid (HID/TN = 4, MTOT/TM = 512), 256 threads, warp tile 64x64
// B fragments software-pipelined (double-buffered) across the 8 k8-steps
// ============================================================
__global__ void __launch_bounds__(256, 1) gemm_score_kernel(
    const float* __restrict__ mem, const float* __restrict__ v)
{
    extern __shared__ float dsm[];
    __shared__ float hxs[TN], vt[TN];

    const int tid  = threadIdx.x;
    const int wid  = tid >> 5, lane = tid & 31;
    const int wm   = wid >> 2, wn = wid & 3;       // 2 x 4 warp grid
    const int tg   = lane >> 2, tig = lane & 3;
    const int  nb  = blockIdx.x;                   // N-block id (0..3)
    const int  n0  = nb * TN;                      // global h base
    const long g0  = (long)blockIdx.y * TM;        // global row base
    const int  b   = blockIdx.y >> 4;              // SL/TM = 16 M-tiles per batch

    if (tid < TN) {
        hxs[tid] = g_hx[b * HID + n0 + tid];
        vt[tid]  = v[n0 + tid];
    }

    const uint32_t sbase = smem_u32(dsm);
    const float* Ag = mem + g0 * MEMD;
    const float* Bg = g_W2T + (long)n0 * MEMD;

    // ldmatrix per-thread address pieces (identical per 32-K half)
    const int lane7 = lane & 7;
    const uint32_t rowA0 = (uint32_t)((wm * 64 + ((lane >> 3) & 1) * 8 + lane7) * 128);
    const uint32_t rowB0 = (uint32_t)((wn * 64 + ((lane >> 4) & 1) * 8 + lane7) * 128);
    const int cbA = (lane >> 4) & 1, cbB = (lane >> 3) & 1;
    uint32_t ofsA[4], ofsB[4];
    #pragma unroll
    for (int ks = 0; ks < 4; ks++) {
        ofsA[ks] = (uint32_t)(((2 * ks + cbA) ^ lane7) << 4);
        ofsB[ks] = (uint32_t)(((2 * ks + cbB) ^ lane7) << 4);
    }

    float acc[4][8][4];
    #pragma unroll
    for (int i = 0; i < 4; i++)
        #pragma unroll
        for (int j = 0; j < 8; j++)
            #pragma unroll
            for (int k = 0; k < 4; k++) acc[i][j][k] = 0.f;

    // prologue: stage 0 (both halves)
    load_half(tid, sbase,              Ag,      Bg);
    load_half(tid, sbase + HALF_BYTES, Ag + 32, Bg + 32);
    CP_COMMIT();

    // B-fragment prefetch helper (flattened step f: half = f>>2, ks = f&3)
    #define LOAD_BFRAGS(dst, stg_, f_) do {                                        \
        const int _h = (f_) >> 2, _ks = (f_) & 3;                                  \
        const uint32_t _sB = (stg_) + (uint32_t)_h * HALF_BYTES + HALF_A;          \
        _Pragma("unroll")                                                          \
        for (int p = 0; p < 4; p++)                                                \
            LDSM4((dst)[p], _sB + rowB0 + (uint32_t)(p * 2048) + ofsB[_ks]);       \
    } while (0)

    for (int it = 0; it < NKITER; it++) {
        CP_WAIT0();
        __syncthreads();

        if (it + 1 < NKITER) {    // prefetch next stage into the other buffer
            uint32_t st = sbase + (uint32_t)((it + 1) & 1) * STG_BYTES;
            const float* Ain = Ag + (it + 1) * KC;
            const float* Bin = Bg + (it + 1) * KC;
            load_half(tid, st,              Ain,      Bin);
            load_half(tid, st + HALF_BYTES, Ain + 32, Bin + 32);
            CP_COMMIT();
        }

        const uint32_t stg = sbase + (uint32_t)(it & 1) * STG_BYTES;

        uint32_t bfd[2][4][4];
        LOAD_BFRAGS(bfd[0], stg, 0);

        #pragma unroll
        for (int f = 0; f < 8; f++) {
            const int h = f >> 2, ks = f & 3;
            const uint32_t sA = stg + (uint32_t)h * HALF_BYTES;
            uint32_t a[4][4];
            #pragma unroll
            for (int mi = 0; mi < 4; mi++)
                LDSM4(a[mi], sA + rowA0 + (uint32_t)(mi * 2048) + ofsA[ks]);
            if (f < 7) LOAD_BFRAGS(bfd[(f + 1) & 1], stg, f + 1);
            const uint32_t (*bb)[4] = bfd[f & 1];
            #pragma unroll
            for (int mi = 0; mi < 4; mi++)
                #pragma unroll
                for (int p = 0; p < 4; p++) {
                    mma_tf32(acc[mi][2 * p],     a[mi], &bb[p][0]);
                    mma_tf32(acc[mi][2 * p + 1], a[mi], &bb[p][2]);
                }
        }
    }
    __syncthreads();

    // Epilogue: partial logit over this warp's 64 h-columns; one writer per
    // (nb, wn, row) slot -> plain store, race-free, deterministic.
    #pragma unroll
    for (int mi = 0; mi < 4; mi++) {
        float p0 = 0.f, p1 = 0.f;
        #pragma unroll
        for (int ni = 0; ni < 8; ni++) {
            int col = wn * 64 + ni * 8 + tig * 2;
            float v0 = vt[col], v1 = vt[col + 1];
            float h0 = hxs[col], h1 = hxs[col + 1];
            p0 += v0 * fast_tanh(h0 + acc[mi][ni][0]) + v1 * fast_tanh(h1 + acc[mi][ni][1]);
            p1 += v0 * fast_tanh(h0 + acc[mi][ni][2]) + v1 * fast_tanh(h1 + acc[mi][ni][3]);
        }
        p0 += __shfl_xor_sync(0xFFFFFFFFu, p0, 1);
        p0 += __shfl_xor_sync(0xFFFFFFFFu, p0, 2);
        p1 += __shfl_xor_sync(0xFFFFFFFFu, p1, 1);
        p1 += __shfl_xor_sync(0xFFFFFFFFu, p1, 2);
        if (tig == 0) {
            long r = g0 + wm * 64 + mi * 16 + tg;
            g_logitsp[nb][wn][r]     = p0;
            g_logitsp[nb][wn][r + 8] = p1;
        }
    }
}

// ============================================================
// Small kernels
// ============================================================
__global__ void transpose_w2_kernel(const float* __restrict__ W2) {
    __shared__ float t[32][33];
    int d0 = blockIdx.x * 32, h0 = blockIdx.y * 32;
    int tx = threadIdx.x, ty = threadIdx.y;
    #pragma unroll
    for (int i = 0; i < 32; i += 8)
        t[ty + i][tx] = W2[(long)(d0 + ty + i) * HID + h0 + tx];
    __syncthreads();
    #pragma unroll
    for (int i = 0; i < 32; i += 8)
        g_W2T[(long)(h0 + ty + i) * MEMD + d0 + tx] = t[tx][ty + i];
}

__global__ void __launch_bounds__(256) hx_kernel(
    const float* __restrict__ x, const float* __restrict__ W1,
    const float* __restrict__ b1, const float* __restrict__ b2)
{
    int h = blockIdx.x * 256 + threadIdx.x;
    int b = blockIdx.y;
    const float* xr = x + b * IND;
    float acc = 0.f;
    #pragma unroll 8
    for (int d = 0; d < IND; d++)
        acc += xr[d] * W1[(long)d * HID + h];
    g_hx[b * HID + h] = acc + b1[h] + b2[h];
}

__global__ void __launch_bounds__(256) softmax_kernel(float* __restrict__ out) {
    __shared__ float buf[SL];
    __shared__ float red[256];
    const int b = blockIdx.x, tid = threadIdx.x;
    const float* lp = &g_logitsp[0][0][0];
    float m = -1e30f;
    for (int s = tid; s < SL; s += 256) {
        int i = b * SL + s;
        float l = 0.f;
        #pragma unroll
        for (int j = 0; j < 16; j++)
            l += lp[j * MTOT + i];
        buf[s] = l;
        m = fmaxf(m, l);
    }
    red[tid] = m; __syncthreads();
    for (int o = 128; o > 0; o >>= 1) {
        if (tid < o) red[tid] = fmaxf(red[tid], red[tid + o]);
        __syncthreads();
    }
    m = red[0]; __syncthreads();
    float sum = 0.f;
    for (int s = tid; s < SL; s += 256) {
        float e = __expf(buf[s] - m);
        buf[s] = e;
        sum += e;
    }
    red[tid] = sum; __syncthreads();
    for (int o = 128; o > 0; o >>= 1) {
        if (tid < o) red[tid] += red[tid + o];
        __syncthreads();
    }
    float inv = 1.f / red[0];
    for (int s = tid; s < SL; s += 256)
        out[OUT_SCORE_OFF + b * SL + s] = buf[s] * inv;
}

// context partials: grid (SCH, BS), 512 threads; 128 seq rows per CTA, dual accumulators
__global__ void __launch_bounds__(512) context_partial_kernel(
    const float* __restrict__ mem, const float* __restrict__ out)
{
    const int sc = blockIdx.x, b = blockIdx.y;
    const int d4 = threadIdx.x;                       // 0..511
    const float*  sp = out + OUT_SCORE_OFF + b * SL + sc * SROWS;
    const float4* mb = (const float4*)(mem + ((long)b * SL + sc * SROWS) * MEMD) + d4;
    float4 a0 = make_float4(0.f, 0.f, 0.f, 0.f);
    float4 a1 = make_float4(0.f, 0.f, 0.f, 0.f);
    #pragma unroll 4
    for (int s = 0; s < SROWS; s += 2) {
        float  w0 = sp[s],      w1 = sp[s + 1];
        float4 m0 = mb[(long)s * (MEMD / 4)];
        float4 m1 = mb[(long)(s + 1) * (MEMD / 4)];
        a0.x += w0 * m0.x; a0.y += w0 * m0.y; a0.z += w0 * m0.z; a0.w += w0 * m0.w;
        a1.x += w1 * m1.x; a1.y += w1 * m1.y; a1.z += w1 * m1.z; a1.w += w1 * m1.w;
    }
    a0.x += a1.x; a0.y += a1.y; a0.z += a1.z; a0.w += a1.w;
    g_ctxp[sc][b][d4] = a0;
}

__global__ void __launch_bounds__(256) ctx_reduce_kernel(float* __restrict__ out) {
    const int i  = blockIdx.x * 256 + threadIdx.x;    // 0..16383 float4 slots
    const int b  = i / (MEMD / 4), d4 = i % (MEMD / 4);
    float4 s = make_float4(0.f, 0.f, 0.f, 0.f);
    #pragma unroll
    for (int c = 0; c < SCH; c++) {
        float4 p = g_ctxp[c][b][d4];
        s.x += p.x; s.y += p.y; s.z += p.z; s.w += p.w;
    }
    ((float4*)out)[i] = s;
}

// ============================================================
// Launch
// ============================================================
extern "C" void kernel_launch(void* const* d_in, const int* in_sizes, int n_in,
                              void* d_out, int out_size)
{
    const float* x      = (const float*)d_in[0];
    const float* memory = (const float*)d_in[1];
    const float* W1     = (const float*)d_in[2];
    const float* b1     = (const float*)d_in[3];
    const float* W2     = (const float*)d_in[4];
    const float* b2     = (const float*)d_in[5];
    const float* v      = (const float*)d_in[6];
    // d_in[7] = bv: cancels under softmax (shift invariance), unused.
    float* out = (float*)d_out;

    cudaFuncSetAttribute(gemm_score_kernel,
                         cudaFuncAttributeMaxDynamicSharedMemorySize, SMEM_GEMM);

    transpose_w2_kernel<<<dim3(MEMD / 32, HID / 32), dim3(32, 8)>>>(W2);
    hx_kernel<<<dim3(HID / 256, BS), 256>>>(x, W1, b1, b2);
    gemm_score_kernel<<<dim3(HID / TN, MTOT / TM), 256, SMEM_GEMM>>>(memory, v);
    softmax_kernel<<<BS, 256>>>(out);
    context_partial_kernel<<<dim3(SCH, BS), 512>>>(memory, out);
    ctx_reduce_kernel<<<BS * MEMD / 4 / 256, 256>>>(out);
}

// round 10
// speedup vs baseline: 1.4629x; 1.4629x over previous
#include <cuda_runtime.h>
#include <cuda_fp16.h>
#include <cstdint>

// ---------------- problem constants ----------------
#define BS    32
#define SL    2048
#define MEMD  2048                // K of the big GEMM
#define HID   1024                // N of the big GEMM
#define IND   1024
#define MTOT  (BS * SL)           // 65536 GEMM rows (M)
#define OUT_SCORE_OFF (BS * MEMD) // context [32,2048] first, then score [32,2048]

// ---------------- GEMM tiling (fp16) ----------------
#define TM       128
#define TN       256
#define KC       64               // K elems per stage = one 128-B fp16 row
#define NKITER   (MEMD / KC)      // 32
#define A_BYTES  (TM * KC * 2)              // 16384
#define B_BYTES  (TN * KC * 2)              // 32768
#define STG_BYTES (A_BYTES + B_BYTES)       // 49152
#define SMEM_GEMM (2 * STG_BYTES)           // 98304 (double buffer)

// ---------------- context tiling ----------------
#define SCH   16
#define SROWS (SL / SCH)          // 128

// ---------------- device scratch (static, no allocations) ----------------
__device__ __half g_memh[(long)MTOT * MEMD];   // fp16 copy of memory (256 MB, bss)
__device__ __half g_W2Th[HID * MEMD];          // W2 transposed fp16: [h][d], K-major
__device__ float  g_hx[BS * HID];              // x@W1 + b1 + b2
// logit partials: [N-block][wn-warp][row] — one writer per slot, deterministic
__device__ float  g_logitsp[4][4][MTOT];
__device__ float4 g_ctxp[SCH][BS][MEMD / 4];   // context partials, 4 MB

// ---------------- helpers ----------------
__device__ __forceinline__ uint32_t smem_u32(const void* p) {
    uint32_t a;
    asm("{ .reg .u64 t; cvta.to.shared.u64 t, %1; cvt.u32.u64 %0, t; }" : "=r"(a) : "l"(p));
    return a;
}
#define CP_ASYNC16(dst, src) \
    asm volatile("cp.async.cg.shared.global [%0], [%1], 16;" :: "r"(dst), "l"(src) : "memory")
#define CP_COMMIT() asm volatile("cp.async.commit_group;" ::: "memory")
#define CP_WAIT0()  asm volatile("cp.async.wait_group 0;" ::: "memory")

// ldmatrix x4: four 8x8 b16 tiles (native fp16 use)
#define LDSM4(r, addr) \
    asm volatile("ldmatrix.sync.aligned.m8n8.x4.shared.b16 {%0,%1,%2,%3}, [%4];" \
        : "=r"((r)[0]), "=r"((r)[1]), "=r"((r)[2]), "=r"((r)[3]) : "r"(addr))

// fp16 MMA, fp32 accumulate: m16n8k16 — 2x MAC/instr vs tf32 m16n8k8
__device__ __forceinline__ void mma_f16(float* c, const uint32_t* a, const uint32_t* b) {
    asm volatile(
        "mma.sync.aligned.m16n8k16.row.col.f32.f16.f16.f32 "
        "{%0,%1,%2,%3}, {%4,%5,%6,%7}, {%8,%9}, {%0,%1,%2,%3};"
        : "+f"(c[0]), "+f"(c[1]), "+f"(c[2]), "+f"(c[3])
        : "r"(a[0]), "r"(a[1]), "r"(a[2]), "r"(a[3]), "r"(b[0]), "r"(b[1]));
}

__device__ __forceinline__ float fast_tanh(float x) {
    float t; asm("tanh.approx.f32 %0, %1;" : "=f"(t) : "f"(x));
    return t;
}

__device__ __forceinline__ uint32_t pack_h2(float a, float b) {
    __half2 h = __floats2half2_rn(a, b);
    return *(uint32_t*)&h;
}

// ============================================================
// memory fp32 -> fp16 (one pass; 768 MB HBM traffic)
// each thread: 8 floats in (2 float4), 8 halves out (1 uint4)
// ============================================================
__global__ void __launch_bounds__(256) convert_mem_kernel(const float4* __restrict__ in) {
    long i = (long)blockIdx.x * 256 + threadIdx.x;   // 0 .. MTOT*MEMD/8-1
    float4 f0 = in[2 * i], f1 = in[2 * i + 1];
    uint4 v;
    v.x = pack_h2(f0.x, f0.y);
    v.y = pack_h2(f0.z, f0.w);
    v.z = pack_h2(f1.x, f1.y);
    v.w = pack_h2(f1.z, f1.w);
    ((uint4*)g_memh)[i] = v;
}

// ============================================================
// Stage loader: A [128 x 64] + B [256 x 64] fp16, 128-B rows, swizzled
// row layout: 8 chunks of 16 B (8 fp16), chunk index XOR (row & 7)
// ============================================================
__device__ __forceinline__ void load_stage(
    int tid, uint32_t st,
    const __half* __restrict__ Ag, const __half* __restrict__ Bg)
{
    #pragma unroll
    for (int o = tid; o < TM * 8; o += 256) {
        int r = o >> 3, ch = o & 7;
        uint32_t dst = st + (uint32_t)(r * 128 + ((ch ^ (r & 7)) << 4));
        CP_ASYNC16(dst, Ag + (long)r * MEMD + ch * 8);
    }
    #pragma unroll
    for (int o = tid; o < TN * 8; o += 256) {
        int r = o >> 3, ch = o & 7;
        uint32_t dst = st + A_BYTES + (uint32_t)(r * 128 + ((ch ^ (r & 7)) << 4));
        CP_ASYNC16(dst, Bg + (long)r * MEMD + ch * 8);
    }
    CP_COMMIT();
}

// ============================================================
// GEMM (memory @ W2T, fp16 x fp16 -> fp32) fused with tanh/v-dot -> logit partials
// grid (HID/TN = 4, MTOT/TM = 512), 256 threads, warp tile 64x64
// ============================================================
__global__ void __launch_bounds__(256, 1) gemm_score_kernel(const float* __restrict__ v)
{
    extern __shared__ float dsm[];
    __shared__ float hxs[TN], vt[TN];

    const int tid  = threadIdx.x;
    const int wid  = tid >> 5, lane = tid & 31;
    const int wm   = wid >> 2, wn = wid & 3;       // 2 x 4 warp grid
    const int tg   = lane >> 2, tig = lane & 3;
    const int  nb  = blockIdx.x;                   // N-block id (0..3)
    const int  n0  = nb * TN;                      // global h base
    const long g0  = (long)blockIdx.y * TM;        // global row base
    const int  b   = blockIdx.y >> 4;              // SL/TM = 16 M-tiles per batch

    if (tid < TN) {
        hxs[tid] = g_hx[b * HID + n0 + tid];
        vt[tid]  = v[n0 + tid];
    }

    const uint32_t sbase = smem_u32(dsm);
    const __half* Ag = g_memh + g0 * MEMD;
    const __half* Bg = g_W2Th + (long)n0 * MEMD;

    // ldmatrix per-thread address pieces (byte-identical geometry to tf32 version)
    // A x4 tiles: (r0-7,k0)(r8-15,k0)(r0-7,k1)(r8-15,k1); B x4: (n0-7,k0)(n0-7,k1)(n8-15,k0)(n8-15,k1)
    const int lane7 = lane & 7;
    const uint32_t rowA0 = (uint32_t)((wm * 64 + ((lane >> 3) & 1) * 8 + lane7) * 128);
    const uint32_t rowB0 = (uint32_t)((wn * 64 + ((lane >> 4) & 1) * 8 + lane7) * 128);
    const int cbA = (lane >> 4) & 1, cbB = (lane >> 3) & 1;
    uint32_t ofsA[4], ofsB[4];
    #pragma unroll
    for (int ks = 0; ks < 4; ks++) {               // 4 k16-steps per 64-K stage
        ofsA[ks] = (uint32_t)(((2 * ks + cbA) ^ lane7) << 4);
        ofsB[ks] = (uint32_t)(((2 * ks + cbB) ^ lane7) << 4);
    }

    float acc[4][8][4];
    #pragma unroll
    for (int i = 0; i < 4; i++)
        #pragma unroll
        for (int j = 0; j < 8; j++)
            #pragma unroll
            for (int k = 0; k < 4; k++) acc[i][j][k] = 0.f;

    // prologue: stage 0
    load_stage(tid, sbase, Ag, Bg);

    for (int it = 0; it < NKITER; it++) {
        CP_WAIT0();
        __syncthreads();

        if (it + 1 < NKITER) {    // prefetch next stage into the other buffer
            load_stage(tid, sbase + (uint32_t)((it + 1) & 1) * STG_BYTES,
                       Ag + (it + 1) * KC, Bg + (it + 1) * KC);
        }

        const uint32_t sA = sbase + (uint32_t)(it & 1) * STG_BYTES;
        const uint32_t sB = sA + A_BYTES;

        #pragma unroll
        for (int ks = 0; ks < 4; ks++) {           // each ks consumes K=16
            uint32_t a[4][4], bf[4][4];
            #pragma unroll
            for (int mi = 0; mi < 4; mi++)
                LDSM4(a[mi], sA + rowA0 + (uint32_t)(mi * 2048) + ofsA[ks]);
            #pragma unroll
            for (int p = 0; p < 4; p++)            // each covers n16
                LDSM4(bf[p], sB + rowB0 + (uint32_t)(p * 2048) + ofsB[ks]);
            #pragma unroll
            for (int mi = 0; mi < 4; mi++)
                #pragma unroll
                for (int p = 0; p < 4; p++) {
                    mma_f16(acc[mi][2 * p],     a[mi], &bf[p][0]);
                    mma_f16(acc[mi][2 * p + 1], a[mi], &bf[p][2]);
                }
        }
    }
    __syncthreads();

    // Epilogue: partial logit over this warp's 64 h-columns; one writer per
    // (nb, wn, row) slot -> plain store, race-free, deterministic.
    #pragma unroll
    for (int mi = 0; mi < 4; mi++) {
        float p0 = 0.f, p1 = 0.f;
        #pragma unroll
        for (int ni = 0; ni < 8; ni++) {
            int col = wn * 64 + ni * 8 + tig * 2;
            float v0 = vt[col], v1 = vt[col + 1];
            float h0 = hxs[col], h1 = hxs[col + 1];
            p0 += v0 * fast_tanh(h0 + acc[mi][ni][0]) + v1 * fast_tanh(h1 + acc[mi][ni][1]);
            p1 += v0 * fast_tanh(h0 + acc[mi][ni][2]) + v1 * fast_tanh(h1 + acc[mi][ni][3]);
        }
        p0 += __shfl_xor_sync(0xFFFFFFFFu, p0, 1);
        p0 += __shfl_xor_sync(0xFFFFFFFFu, p0, 2);
        p1 += __shfl_xor_sync(0xFFFFFFFFu, p1, 1);
        p1 += __shfl_xor_sync(0xFFFFFFFFu, p1, 2);
        if (tig == 0) {
            long r = g0 + wm * 64 + mi * 16 + tg;
            g_logitsp[nb][wn][r]     = p0;
            g_logitsp[nb][wn][r + 8] = p1;
        }
    }
}

// ============================================================
// Small kernels
// ============================================================
__global__ void transpose_w2_kernel(const float* __restrict__ W2) {
    __shared__ float t[32][33];
    int d0 = blockIdx.x * 32, h0 = blockIdx.y * 32;
    int tx = threadIdx.x, ty = threadIdx.y;
    #pragma unroll
    for (int i = 0; i < 32; i += 8)
        t[ty + i][tx] = W2[(long)(d0 + ty + i) * HID + h0 + tx];
    __syncthreads();
    #pragma unroll
    for (int i = 0; i < 32; i += 8)
        g_W2Th[(long)(h0 + ty + i) * MEMD + d0 + tx] = __float2half(t[tx][ty + i]);
}

__global__ void __launch_bounds__(256) hx_kernel(
    const float* __restrict__ x, const float* __restrict__ W1,
    const float* __restrict__ b1, const float* __restrict__ b2)
{
    int h = blockIdx.x * 256 + threadIdx.x;
    int b = blockIdx.y;
    const float* xr = x + b * IND;
    float acc = 0.f;
    #pragma unroll 8
    for (int d = 0; d < IND; d++)
        acc += xr[d] * W1[(long)d * HID + h];
    g_hx[b * HID + h] = acc + b1[h] + b2[h];
}

__global__ void __launch_bounds__(256) softmax_kernel(float* __restrict__ out) {
    __shared__ float buf[SL];
    __shared__ float red[256];
    const int b = blockIdx.x, tid = threadIdx.x;
    const float* lp = &g_logitsp[0][0][0];
    float m = -1e30f;
    for (int s = tid; s < SL; s += 256) {
        int i = b * SL + s;
        float l = 0.f;
        #pragma unroll
        for (int j = 0; j < 16; j++)
            l += lp[j * MTOT + i];
        buf[s] = l;
        m = fmaxf(m, l);
    }
    red[tid] = m; __syncthreads();
    for (int o = 128; o > 0; o >>= 1) {
        if (tid < o) red[tid] = fmaxf(red[tid], red[tid + o]);
        __syncthreads();
    }
    m = red[0]; __syncthreads();
    float sum = 0.f;
    for (int s = tid; s < SL; s += 256) {
        float e = __expf(buf[s] - m);
        buf[s] = e;
        sum += e;
    }
    red[tid] = sum; __syncthreads();
    for (int o = 128; o > 0; o >>= 1) {
        if (tid < o) red[tid] += red[tid + o];
        __syncthreads();
    }
    float inv = 1.f / red[0];
    for (int s = tid; s < SL; s += 256)
        out[OUT_SCORE_OFF + b * SL + s] = buf[s] * inv;
}

// context partials: grid (SCH, BS), 512 threads; 128 seq rows per CTA (fp32 memory)
__global__ void __launch_bounds__(512) context_partial_kernel(
    const float* __restrict__ mem, const float* __restrict__ out)
{
    const int sc = blockIdx.x, b = blockIdx.y;
    const int d4 = threadIdx.x;                       // 0..511
    const float*  sp = out + OUT_SCORE_OFF + b * SL + sc * SROWS;
    const float4* mb = (const float4*)(mem + ((long)b * SL + sc * SROWS) * MEMD) + d4;
    float4 a0 = make_float4(0.f, 0.f, 0.f, 0.f);
    float4 a1 = make_float4(0.f, 0.f, 0.f, 0.f);
    #pragma unroll 4
    for (int s = 0; s < SROWS; s += 2) {
        float  w0 = sp[s],      w1 = sp[s + 1];
        float4 m0 = mb[(long)s * (MEMD / 4)];
        float4 m1 = mb[(long)(s + 1) * (MEMD / 4)];
        a0.x += w0 * m0.x; a0.y += w0 * m0.y; a0.z += w0 * m0.z; a0.w += w0 * m0.w;
        a1.x += w1 * m1.x; a1.y += w1 * m1.y; a1.z += w1 * m1.z; a1.w += w1 * m1.w;
    }
    a0.x += a1.x; a0.y += a1.y; a0.z += a1.z; a0.w += a1.w;
    g_ctxp[sc][b][d4] = a0;
}

__global__ void __launch_bounds__(256) ctx_reduce_kernel(float* __restrict__ out) {
    const int i  = blockIdx.x * 256 + threadIdx.x;    // 0..16383 float4 slots
    const int b  = i / (MEMD / 4), d4 = i % (MEMD / 4);
    float4 s = make_float4(0.f, 0.f, 0.f, 0.f);
    #pragma unroll
    for (int c = 0; c < SCH; c++) {
        float4 p = g_ctxp[c][b][d4];
        s.x += p.x; s.y += p.y; s.z += p.z; s.w += p.w;
    }
    ((float4*)out)[i] = s;
}

// ============================================================
// Launch
// ============================================================
extern "C" void kernel_launch(void* const* d_in, const int* in_sizes, int n_in,
                              void* d_out, int out_size)
{
    const float* x      = (const float*)d_in[0];
    const float* memory = (const float*)d_in[1];
    const float* W1     = (const float*)d_in[2];
    const float* b1     = (const float*)d_in[3];
    const float* W2     = (const float*)d_in[4];
    const float* b2     = (const float*)d_in[5];
    const float* v      = (const float*)d_in[6];
    // d_in[7] = bv: cancels under softmax (shift invariance), unused.
    float* out = (float*)d_out;

    cudaFuncSetAttribute(gemm_score_kernel,
                         cudaFuncAttributeMaxDynamicSharedMemorySize, SMEM_GEMM);

    convert_mem_kernel<<<(int)((long)MTOT * MEMD / 8 / 256), 256>>>((const float4*)memory);
    transpose_w2_kernel<<<dim3(MEMD / 32, HID / 32), dim3(32, 8)>>>(W2);
    hx_kernel<<<dim3(HID / 256, BS), 256>>>(x, W1, b1, b2);
    gemm_score_kernel<<<dim3(HID / TN, MTOT / TM), 256, SMEM_GEMM>>>(v);
    softmax_kernel<<<BS, 256>>>(out);
    context_partial_kernel<<<dim3(SCH, BS), 512>>>(memory, out);
    ctx_reduce_kernel<<<BS * MEMD / 4 / 256, 256>>>(out);
}

// round 11
// speedup vs baseline: 1.5792x; 1.0795x over previous
#include <cuda_runtime.h>
#include <cuda_fp16.h>
#include <cstdint>

// ---------------- problem constants ----------------
#define BS    32
#define SL    2048
#define MEMD  2048                // K of the big GEMM
#define HID   1024                // N of the big GEMM
#define IND   1024
#define MTOT  (BS * SL)           // 65536 GEMM rows (M)
#define OUT_SCORE_OFF (BS * MEMD) // context [32,2048] first, then score [32,2048]

// ---------------- GEMM tiling (fp16) ----------------
#define TM       128
#define TN       256
#define KC       128              // K elems per stage = 2 sub-tiles of 64
#define NKITER   (MEMD / KC)      // 16
#define HALF_A   (TM * 64 * 2)              // 16384 B
#define HALF_B   (TN * 64 * 2)              // 32768 B
#define HALF_BYTES (HALF_A + HALF_B)        // 49152 B
#define STG_BYTES  (2 * HALF_BYTES)         // 98304 B
#define SMEM_GEMM  (2 * STG_BYTES)          // 196608 B (double buffer)

// ---------------- context tiling ----------------
#define SCH   16
#define SROWS (SL / SCH)          // 128

// ---------------- device scratch (static, no allocations) ----------------
__device__ __half g_memh[(long)MTOT * MEMD];   // fp16 copy of memory (256 MB, bss)
__device__ __half g_W2Th[HID * MEMD];          // W2 transposed fp16: [h][d], K-major
__device__ float  g_hx[BS * HID];              // x@W1 + b1 + b2
// logit partials: [N-block][wn-warp][row] — one writer per slot, deterministic
__device__ float  g_logitsp[4][4][MTOT];
__device__ float4 g_ctxp[SCH][BS][MEMD / 4];   // context partials, 4 MB

// ---------------- helpers ----------------
__device__ __forceinline__ uint32_t smem_u32(const void* p) {
    uint32_t a;
    asm("{ .reg .u64 t; cvta.to.shared.u64 t, %1; cvt.u32.u64 %0, t; }" : "=r"(a) : "l"(p));
    return a;
}
#define CP_ASYNC16(dst, src) \
    asm volatile("cp.async.cg.shared.global [%0], [%1], 16;" :: "r"(dst), "l"(src) : "memory")
#define CP_COMMIT() asm volatile("cp.async.commit_group;" ::: "memory")
#define CP_WAIT0()  asm volatile("cp.async.wait_group 0;" ::: "memory")

// ldmatrix x4: four 8x8 b16 tiles (native fp16 use)
#define LDSM4(r, addr) \
    asm volatile("ldmatrix.sync.aligned.m8n8.x4.shared.b16 {%0,%1,%2,%3}, [%4];" \
        : "=r"((r)[0]), "=r"((r)[1]), "=r"((r)[2]), "=r"((r)[3]) : "r"(addr))

// fp16 MMA, fp32 accumulate: m16n8k16
__device__ __forceinline__ void mma_f16(float* c, const uint32_t* a, const uint32_t* b) {
    asm volatile(
        "mma.sync.aligned.m16n8k16.row.col.f32.f16.f16.f32 "
        "{%0,%1,%2,%3}, {%4,%5,%6,%7}, {%8,%9}, {%0,%1,%2,%3};"
        : "+f"(c[0]), "+f"(c[1]), "+f"(c[2]), "+f"(c[3])
        : "r"(a[0]), "r"(a[1]), "r"(a[2]), "r"(a[3]), "r"(b[0]), "r"(b[1]));
}

__device__ __forceinline__ float fast_tanh(float x) {
    float t; asm("tanh.approx.f32 %0, %1;" : "=f"(t) : "f"(x));
    return t;
}

__device__ __forceinline__ uint32_t pack_h2(float a, float b) {
    __half2 h = __floats2half2_rn(a, b);
    return *(uint32_t*)&h;
}

// ============================================================
// memory fp32 -> fp16 (one pass; 768 MB HBM traffic)
// ============================================================
__global__ void __launch_bounds__(256) convert_mem_kernel(const float4* __restrict__ in) {
    long i = (long)blockIdx.x * 256 + threadIdx.x;   // 0 .. MTOT*MEMD/8-1
    float4 f0 = in[2 * i], f1 = in[2 * i + 1];
    uint4 v;
    v.x = pack_h2(f0.x, f0.y);
    v.y = pack_h2(f0.z, f0.w);
    v.z = pack_h2(f1.x, f1.y);
    v.w = pack_h2(f1.z, f1.w);
    ((uint4*)g_memh)[i] = v;
}

// ============================================================
// Half-stage loader: A [128 x 64] + B [256 x 64] fp16, 128-B rows, swizzled
// row layout: 8 chunks of 16 B (8 fp16), chunk index XOR (row & 7)
// ============================================================
__device__ __forceinline__ void load_half(
    int tid, uint32_t st,
    const __half* __restrict__ Ag, const __half* __restrict__ Bg)
{
    #pragma unroll
    for (int o = tid; o < TM * 8; o += 256) {
        int r = o >> 3, ch = o & 7;
        uint32_t dst = st + (uint32_t)(r * 128 + ((ch ^ (r & 7)) << 4));
        CP_ASYNC16(dst, Ag + (long)r * MEMD + ch * 8);
    }
    #pragma unroll
    for (int o = tid; o < TN * 8; o += 256) {
        int r = o >> 3, ch = o & 7;
        uint32_t dst = st + HALF_A + (uint32_t)(r * 128 + ((ch ^ (r & 7)) << 4));
        CP_ASYNC16(dst, Bg + (long)r * MEMD + ch * 8);
    }
}

// ============================================================
// GEMM (memory @ W2T, fp16 -> fp32) fused with tanh/v-dot -> logit partials
// grid (HID/TN = 4, MTOT/TM = 512), 256 threads, warp tile 64x64
// ============================================================
__global__ void __launch_bounds__(256, 1) gemm_score_kernel(const float* __restrict__ v)
{
    extern __shared__ float dsm[];
    __shared__ float hxs[TN], vt[TN];

    const int tid  = threadIdx.x;
    const int wid  = tid >> 5, lane = tid & 31;
    const int wm   = wid >> 2, wn = wid & 3;       // 2 x 4 warp grid
    const int tg   = lane >> 2, tig = lane & 3;
    const int  nb  = blockIdx.x;                   // N-block id (0..3)
    const int  n0  = nb * TN;                      // global h base
    const long g0  = (long)blockIdx.y * TM;        // global row base
    const int  b   = blockIdx.y >> 4;              // SL/TM = 16 M-tiles per batch

    if (tid < TN) {
        hxs[tid] = g_hx[b * HID + n0 + tid];
        vt[tid]  = v[n0 + tid];
    }

    const uint32_t sbase = smem_u32(dsm);
    const __half* Ag = g_memh + g0 * MEMD;
    const __half* Bg = g_W2Th + (long)n0 * MEMD;

    // ldmatrix per-thread address pieces (identical per 64-K half)
    const int lane7 = lane & 7;
    const uint32_t rowA0 = (uint32_t)((wm * 64 + ((lane >> 3) & 1) * 8 + lane7) * 128);
    const uint32_t rowB0 = (uint32_t)((wn * 64 + ((lane >> 4) & 1) * 8 + lane7) * 128);
    const int cbA = (lane >> 4) & 1, cbB = (lane >> 3) & 1;
    uint32_t ofsA[4], ofsB[4];
    #pragma unroll
    for (int ks = 0; ks < 4; ks++) {               // 4 k16-steps per 64-K half
        ofsA[ks] = (uint32_t)(((2 * ks + cbA) ^ lane7) << 4);
        ofsB[ks] = (uint32_t)(((2 * ks + cbB) ^ lane7) << 4);
    }

    float acc[4][8][4];
    #pragma unroll
    for (int i = 0; i < 4; i++)
        #pragma unroll
        for (int j = 0; j < 8; j++)
            #pragma unroll
            for (int k = 0; k < 4; k++) acc[i][j][k] = 0.f;

    // prologue: stage 0 (both halves)
    load_half(tid, sbase,              Ag,      Bg);
    load_half(tid, sbase + HALF_BYTES, Ag + 64, Bg + 64);
    CP_COMMIT();

    for (int it = 0; it < NKITER; it++) {
        CP_WAIT0();
        __syncthreads();

        if (it + 1 < NKITER) {    // prefetch next stage into the other buffer
            uint32_t st = sbase + (uint32_t)((it + 1) & 1) * STG_BYTES;
            const __half* Ain = Ag + (it + 1) * KC;
            const __half* Bin = Bg + (it + 1) * KC;
            load_half(tid, st,              Ain,      Bin);
            load_half(tid, st + HALF_BYTES, Ain + 64, Bin + 64);
            CP_COMMIT();
        }

        const uint32_t stg = sbase + (uint32_t)(it & 1) * STG_BYTES;
        #pragma unroll
        for (int h = 0; h < 2; h++) {
            const uint32_t sA = stg + (uint32_t)h * HALF_BYTES;
            const uint32_t sB = sA + HALF_A;
            #pragma unroll
            for (int ks = 0; ks < 4; ks++) {       // each ks consumes K=16
                uint32_t a[4][4], bf[4][4];
                #pragma unroll
                for (int mi = 0; mi < 4; mi++)
                    LDSM4(a[mi], sA + rowA0 + (uint32_t)(mi * 2048) + ofsA[ks]);
                #pragma unroll
                for (int p = 0; p < 4; p++)        // each covers n16
                    LDSM4(bf[p], sB + rowB0 + (uint32_t)(p * 2048) + ofsB[ks]);
                #pragma unroll
                for (int mi = 0; mi < 4; mi++)
                    #pragma unroll
                    for (int p = 0; p < 4; p++) {
                        mma_f16(acc[mi][2 * p],     a[mi], &bf[p][0]);
                        mma_f16(acc[mi][2 * p + 1], a[mi], &bf[p][2]);
                    }
            }
        }
    }
    __syncthreads();

    // Epilogue: partial logit over this warp's 64 h-columns; one writer per
    // (nb, wn, row) slot -> plain store, race-free, deterministic.
    #pragma unroll
    for (int mi = 0; mi < 4; mi++) {
        float p0 = 0.f, p1 = 0.f;
        #pragma unroll
        for (int ni = 0; ni < 8; ni++) {
            int col = wn * 64 + ni * 8 + tig * 2;
            float v0 = vt[col], v1 = vt[col + 1];
            float h0 = hxs[col], h1 = hxs[col + 1];
            p0 += v0 * fast_tanh(h0 + acc[mi][ni][0]) + v1 * fast_tanh(h1 + acc[mi][ni][1]);
            p1 += v0 * fast_tanh(h0 + acc[mi][ni][2]) + v1 * fast_tanh(h1 + acc[mi][ni][3]);
        }
        p0 += __shfl_xor_sync(0xFFFFFFFFu, p0, 1);
        p0 += __shfl_xor_sync(0xFFFFFFFFu, p0, 2);
        p1 += __shfl_xor_sync(0xFFFFFFFFu, p1, 1);
        p1 += __shfl_xor_sync(0xFFFFFFFFu, p1, 2);
        if (tig == 0) {
            long r = g0 + wm * 64 + mi * 16 + tg;
            g_logitsp[nb][wn][r]     = p0;
            g_logitsp[nb][wn][r + 8] = p1;
        }
    }
}

// ============================================================
// Small kernels
// ============================================================
__global__ void transpose_w2_kernel(const float* __restrict__ W2) {
    __shared__ float t[32][33];
    int d0 = blockIdx.x * 32, h0 = blockIdx.y * 32;
    int tx = threadIdx.x, ty = threadIdx.y;
    #pragma unroll
    for (int i = 0; i < 32; i += 8)
        t[ty + i][tx] = W2[(long)(d0 + ty + i) * HID + h0 + tx];
    __syncthreads();
    #pragma unroll
    for (int i = 0; i < 32; i += 8)
        g_W2Th[(long)(h0 + ty + i) * MEMD + d0 + tx] = __float2half(t[tx][ty + i]);
}

__global__ void __launch_bounds__(256) hx_kernel(
    const float* __restrict__ x, const float* __restrict__ W1,
    const float* __restrict__ b1, const float* __restrict__ b2)
{
    int h = blockIdx.x * 256 + threadIdx.x;
    int b = blockIdx.y;
    const float* xr = x + b * IND;
    float acc = 0.f;
    #pragma unroll 8
    for (int d = 0; d < IND; d++)
        acc += xr[d] * W1[(long)d * HID + h];
    g_hx[b * HID + h] = acc + b1[h] + b2[h];
}

__global__ void __launch_bounds__(256) softmax_kernel(float* __restrict__ out) {
    __shared__ float buf[SL];
    __shared__ float red[256];
    const int b = blockIdx.x, tid = threadIdx.x;
    const float* lp = &g_logitsp[0][0][0];
    float m = -1e30f;
    for (int s = tid; s < SL; s += 256) {
        int i = b * SL + s;
        float l = 0.f;
        #pragma unroll
        for (int j = 0; j < 16; j++)
            l += lp[j * MTOT + i];
        buf[s] = l;
        m = fmaxf(m, l);
    }
    red[tid] = m; __syncthreads();
    for (int o = 128; o > 0; o >>= 1) {
        if (tid < o) red[tid] = fmaxf(red[tid], red[tid + o]);
        __syncthreads();
    }
    m = red[0]; __syncthreads();
    float sum = 0.f;
    for (int s = tid; s < SL; s += 256) {
        float e = __expf(buf[s] - m);
        buf[s] = e;
        sum += e;
    }
    red[tid] = sum; __syncthreads();
    for (int o = 128; o > 0; o >>= 1) {
        if (tid < o) red[tid] += red[tid + o];
        __syncthreads();
    }
    float inv = 1.f / red[0];
    for (int s = tid; s < SL; s += 256)
        out[OUT_SCORE_OFF + b * SL + s] = buf[s] * inv;
}

// context partials from the fp16 memory copy: grid (SCH, BS), 256 threads.
// Each thread accumulates 8 d-columns (one uint4 = 8 halves per row).
__global__ void __launch_bounds__(256) context_partial_kernel(const float* __restrict__ out)
{
    const int sc = blockIdx.x, b = blockIdx.y;
    const int d8 = threadIdx.x;                       // 0..255
    const float* sp = out + OUT_SCORE_OFF + b * SL + sc * SROWS;
    const uint4* mb = (const uint4*)(g_memh + ((long)b * SL + sc * SROWS) * MEMD) + d8;
    float a0[8] = {0,0,0,0,0,0,0,0}, a1[8] = {0,0,0,0,0,0,0,0};
    #pragma unroll 2
    for (int s = 0; s < SROWS; s += 2) {
        float w0 = sp[s], w1 = sp[s + 1];
        uint4 v0 = mb[(long)s * (MEMD / 8)];
        uint4 v1 = mb[(long)(s + 1) * (MEMD / 8)];
        float2 f;
        f = __half22float2(*(__half2*)&v0.x); a0[0] += w0 * f.x; a0[1] += w0 * f.y;
        f = __half22float2(*(__half2*)&v0.y); a0[2] += w0 * f.x; a0[3] += w0 * f.y;
        f = __half22float2(*(__half2*)&v0.z); a0[4] += w0 * f.x; a0[5] += w0 * f.y;
        f = __half22float2(*(__half2*)&v0.w); a0[6] += w0 * f.x; a0[7] += w0 * f.y;
        f = __half22float2(*(__half2*)&v1.x); a1[0] += w1 * f.x; a1[1] += w1 * f.y;
        f = __half22float2(*(__half2*)&v1.y); a1[2] += w1 * f.x; a1[3] += w1 * f.y;
        f = __half22float2(*(__half2*)&v1.z); a1[4] += w1 * f.x; a1[5] += w1 * f.y;
        f = __half22float2(*(__half2*)&v1.w); a1[6] += w1 * f.x; a1[7] += w1 * f.y;
    }
    float4* dst = &g_ctxp[sc][b][2 * d8];
    dst[0] = make_float4(a0[0] + a1[0], a0[1] + a1[1], a0[2] + a1[2], a0[3] + a1[3]);
    dst[1] = make_float4(a0[4] + a1[4], a0[5] + a1[5], a0[6] + a1[6], a0[7] + a1[7]);
}

__global__ void __launch_bounds__(256) ctx_reduce_kernel(float* __restrict__ out) {
    const int i  = blockIdx.x * 256 + threadIdx.x;    // 0..16383 float4 slots
    const int b  = i / (MEMD / 4), d4 = i % (MEMD / 4);
    float4 s = make_float4(0.f, 0.f, 0.f, 0.f);
    #pragma unroll
    for (int c = 0; c < SCH; c++) {
        float4 p = g_ctxp[c][b][d4];
        s.x += p.x; s.y += p.y; s.z += p.z; s.w += p.w;
    }
    ((float4*)out)[i] = s;
}

// ============================================================
// Launch
// ============================================================
extern "C" void kernel_launch(void* const* d_in, const int* in_sizes, int n_in,
                              void* d_out, int out_size)
{
    const float* x      = (const float*)d_in[0];
    const float* memory = (const float*)d_in[1];
    const float* W1     = (const float*)d_in[2];
    const float* b1     = (const float*)d_in[3];
    const float* W2     = (const float*)d_in[4];
    const float* b2     = (const float*)d_in[5];
    const float* v      = (const float*)d_in[6];
    // d_in[7] = bv: cancels under softmax (shift invariance), unused.
    float* out = (float*)d_out;

    cudaFuncSetAttribute(gemm_score_kernel,
                         cudaFuncAttributeMaxDynamicSharedMemorySize, SMEM_GEMM);

    convert_mem_kernel<<<(int)((long)MTOT * MEMD / 8 / 256), 256>>>((const float4*)memory);
    transpose_w2_kernel<<<dim3(MEMD / 32, HID / 32), dim3(32, 8)>>>(W2);
    hx_kernel<<<dim3(HID / 256, BS), 256>>>(x, W1, b1, b2);
    gemm_score_kernel<<<dim3(HID / TN, MTOT / TM), 256, SMEM_GEMM>>>(v);
    softmax_kernel<<<BS, 256>>>(out);
    context_partial_kernel<<<dim3(SCH, BS), 256>>>(out);
    ctx_reduce_kernel<<<BS * MEMD / 4 / 256, 256>>>(out);
}